// round 1
// baseline (speedup 1.0000x reference)
#include <cuda_runtime.h>
#include <math.h>

// Problem constants
#define BB   8
#define CC   64
#define KK   32
#define WH   256
#define HW   65536          // 256*256 pixels per channel
#define NQ   4              // partial-sum quarters per channel

// Output packing (element offsets into d_out, fp32):
//   out  [8,96,256,256]  @ 0
//   exPx [8,32,256,256]  @ 50331648
//   exPy                 @ 67108864
//   sigmax               @ 83886080
//   sigmay               @ 100663296
#define OFF_OUT  0UL
#define OFF_PX   50331648UL
#define OFF_PY   67108864UL
#define OFF_SX   83886080UL
#define OFF_SY   100663296UL

// Scratch (no allocations allowed)
__device__ float g_partial[BB * CC * NQ];
__device__ int   g_idx[BB * KK];

// ---------------------------------------------------------------------------
// Kernel 1: stream x -> copy into out[:, :64] and accumulate per-channel sums.
// grid.x = 512 channels * 4 quarters = 2048 blocks, 256 threads.
// Each quarter = 16384 floats = 4096 float4 ; 16 float4 per thread.
// ---------------------------------------------------------------------------
__global__ void k1_mean_copy(const float* __restrict__ x, float* __restrict__ out) {
    const int bc = blockIdx.x >> 2;   // 0..511 (b*64 + c)
    const int q  = blockIdx.x & 3;
    const int b  = bc >> 6;
    const int c  = bc & 63;

    const float4* __restrict__ src =
        (const float4*)(x + (size_t)bc * HW) + q * 4096;
    float4* __restrict__ dst =
        (float4*)(out + OFF_OUT + ((size_t)b * 96 + c) * HW) + q * 4096;

    float s = 0.0f;
#pragma unroll
    for (int it = 0; it < 16; it++) {
        float4 v = src[it * 256 + threadIdx.x];
        dst[it * 256 + threadIdx.x] = v;
        s += (v.x + v.y) + (v.z + v.w);
    }

    __shared__ float red[256];
    red[threadIdx.x] = s;
    __syncthreads();
#pragma unroll
    for (int st = 128; st > 0; st >>= 1) {
        if (threadIdx.x < st) red[threadIdx.x] += red[threadIdx.x + st];
        __syncthreads();
    }
    if (threadIdx.x == 0) g_partial[bc * NQ + q] = red[0];
}

// ---------------------------------------------------------------------------
// Kernel 2: fold partials -> mean, FC (64x64) + LeakyReLU(0.01), top-32 per
// batch with jax.lax.top_k tie semantics (strict >, lowest index wins).
// Single block, 256 threads. Trivial cost.
// ---------------------------------------------------------------------------
__global__ void k2_fc_topk(const float* __restrict__ fc_w,
                           const float* __restrict__ fc_b) {
    __shared__ float mean_s[BB * CC];
    __shared__ float y_s[BB * CC];
    const int t = threadIdx.x;

    for (int i = t; i < BB * CC; i += 256) {
        float s = g_partial[i * NQ + 0] + g_partial[i * NQ + 1]
                + g_partial[i * NQ + 2] + g_partial[i * NQ + 3];
        mean_s[i] = s * (1.0f / (float)HW);
    }
    __syncthreads();

    for (int i = t; i < BB * CC; i += 256) {
        const int b = i >> 6;
        const int c = i & 63;
        float acc = fc_b[c];
#pragma unroll 8
        for (int j = 0; j < CC; j++)
            acc += mean_s[b * CC + j] * fc_w[c * CC + j];
        y_s[i] = (acc >= 0.0f) ? acc : 0.01f * acc;
    }
    __syncthreads();

    if (t < BB) {
        const int b = t;
        bool used[CC];
#pragma unroll
        for (int j = 0; j < CC; j++) used[j] = false;
        for (int kk = 0; kk < KK; kk++) {
            int best = 0;
            float bv = -3.402823466e38f;
            for (int j = 0; j < CC; j++) {
                float v = y_s[b * CC + j];
                if (!used[j] && v > bv) { bv = v; best = j; }
            }
            used[best] = true;
            g_idx[b * KK + kk] = best;
        }
    }
}

// ---------------------------------------------------------------------------
// Kernel 3: per-pixel Gaussian warp over selected channels.
// grid = (16, 256): blockIdx.y = b*32 + kk ; each thread handles 4 float4
// via grid stride (16*256 threads cover 16384 float4 per channel).
// Reads sel (67 MB), writes swap + 4 aux maps (335 MB).
// ---------------------------------------------------------------------------
__global__ void k3_warp(const float* __restrict__ x,
                        const float* __restrict__ wox, const float* __restrict__ box_,
                        const float* __restrict__ woy, const float* __restrict__ boy,
                        const float* __restrict__ wsx, const float* __restrict__ bsx,
                        const float* __restrict__ wsy, const float* __restrict__ bsy,
                        float* __restrict__ out) {
    const int bk = blockIdx.y;      // 0..255
    const int b  = bk >> 5;
    const int kk = bk & 31;
    const int ch = g_idx[bk];

    const float wx = wox[kk], bx = box_[kk];
    const float wy = woy[kk], by = boy[kk];
    const float wsxk = wsx[kk], bsxk = bsx[kk];
    const float wsyk = wsy[kk], bsyk = bsy[kk];

    const float4* __restrict__ src =
        (const float4*)(x + ((size_t)b * CC + ch) * HW);
    float4* __restrict__ o_sw =
        (float4*)(out + OFF_OUT + ((size_t)b * 96 + 64 + kk) * HW);
    const size_t aux = (size_t)bk * HW;
    float4* __restrict__ o_px = (float4*)(out + OFF_PX + aux);
    float4* __restrict__ o_py = (float4*)(out + OFF_PY + aux);
    float4* __restrict__ o_sx = (float4*)(out + OFF_SX + aux);
    float4* __restrict__ o_sy = (float4*)(out + OFF_SY + aux);

    for (int i4 = blockIdx.x * blockDim.x + threadIdx.x; i4 < (HW / 4);
         i4 += gridDim.x * blockDim.x) {
        float4 v = src[i4];
        const float fi  = (float)(i4 >> 6);          // row (dim 2) coordinate
        const float fj0 = (float)((i4 & 63) << 2);   // col (dim 3) base coord

        float4 px, py, sx, sy, sw;

#define DO_LANE(comp, jo)                                                      \
        {                                                                      \
            float vv  = v.comp;                                                \
            float ex  = 255.0f / (1.0f + expf(-(wx * vv + bx)));               \
            float ey  = 255.0f / (1.0f + expf(-(wy * vv + by)));               \
            float sxx = fabsf(wsxk * vv + bsxk);                               \
            float syy = fabsf(wsyk * vv + bsyk);                               \
            float di  = fi - ex;                                               \
            float dj  = (fj0 + (jo)) - ey;                                     \
            float g   = expf(-(di * di / (2.0f * sxx * sxx + 1e-6f) +          \
                               dj * dj / (2.0f * syy * syy + 1e-6f)));         \
            px.comp = ex; py.comp = ey;                                        \
            sx.comp = sxx; sy.comp = syy;                                      \
            sw.comp = vv * g;                                                  \
        }
        DO_LANE(x, 0.0f)
        DO_LANE(y, 1.0f)
        DO_LANE(z, 2.0f)
        DO_LANE(w, 3.0f)
#undef DO_LANE

        o_sw[i4] = sw;
        o_px[i4] = px;
        o_py[i4] = py;
        o_sx[i4] = sx;
        o_sy[i4] = sy;
    }
}

// ---------------------------------------------------------------------------
extern "C" void kernel_launch(void* const* d_in, const int* in_sizes, int n_in,
                              void* d_out, int out_size) {
    const float* x    = (const float*)d_in[0];
    const float* fc_w = (const float*)d_in[1];
    const float* fc_b = (const float*)d_in[2];
    const float* wox  = (const float*)d_in[3];
    const float* box_ = (const float*)d_in[4];
    const float* woy  = (const float*)d_in[5];
    const float* boy  = (const float*)d_in[6];
    const float* wsx  = (const float*)d_in[7];
    const float* bsx  = (const float*)d_in[8];
    const float* wsy  = (const float*)d_in[9];
    const float* bsy  = (const float*)d_in[10];
    float* out = (float*)d_out;

    k1_mean_copy<<<BB * CC * NQ, 256>>>(x, out);
    k2_fc_topk<<<1, 256>>>(fc_w, fc_b);
    dim3 g3(16, BB * KK);
    k3_warp<<<g3, 256>>>(x, wox, box_, woy, boy, wsx, bsx, wsy, bsy, out);
}

// round 2
// speedup vs baseline: 1.0267x; 1.0267x over previous
#include <cuda_runtime.h>
#include <math.h>

// Problem constants
#define BB   8
#define CC   64
#define KK   32
#define WH   256
#define HW   65536          // 256*256 pixels per channel
#define NQ   4              // partial-sum quarters per channel

// Output packing (element offsets into d_out, fp32):
//   out  [8,96,256,256]  @ 0
//   exPx [8,32,256,256]  @ 50331648
//   exPy                 @ 67108864
//   sigmax               @ 83886080
//   sigmay               @ 100663296
#define OFF_OUT  0UL
#define OFF_PX   50331648UL
#define OFF_PY   67108864UL
#define OFF_SX   83886080UL
#define OFF_SY   100663296UL

// Scratch (no allocations allowed)
__device__ float g_partial[BB * CC * NQ];
__device__ int   g_idx[BB * KK];

// ---------------------------------------------------------------------------
// Kernel 1: stream x -> copy into out[:, :64] and accumulate per-channel sums.
// grid.x = 512 channels * 4 quarters = 2048 blocks, 256 threads.
// Each quarter = 16384 floats = 4096 float4 ; 16 float4 per thread.
// ---------------------------------------------------------------------------
__global__ void k1_mean_copy(const float* __restrict__ x, float* __restrict__ out) {
    const int bc = blockIdx.x >> 2;   // 0..511 (b*64 + c)
    const int q  = blockIdx.x & 3;
    const int b  = bc >> 6;
    const int c  = bc & 63;

    const float4* __restrict__ src =
        (const float4*)(x + (size_t)bc * HW) + q * 4096;
    float4* __restrict__ dst =
        (float4*)(out + OFF_OUT + ((size_t)b * 96 + c) * HW) + q * 4096;

    float s = 0.0f;
#pragma unroll
    for (int it = 0; it < 16; it++) {
        float4 v = __ldcs(&src[it * 256 + threadIdx.x]);
        __stcs(&dst[it * 256 + threadIdx.x], v);
        s += (v.x + v.y) + (v.z + v.w);
    }

    // warp reduce then cross-warp via shared
    for (int off = 16; off > 0; off >>= 1)
        s += __shfl_down_sync(0xffffffffu, s, off);
    __shared__ float red[8];
    if ((threadIdx.x & 31) == 0) red[threadIdx.x >> 5] = s;
    __syncthreads();
    if (threadIdx.x == 0) {
        float t = 0.0f;
#pragma unroll
        for (int w = 0; w < 8; w++) t += red[w];
        g_partial[bc * NQ + q] = t;
    }
}

// ---------------------------------------------------------------------------
// Kernel 2: fold partials -> mean, FC (64x64) + LeakyReLU(0.01), top-32 per
// batch with jax.lax.top_k tie semantics (strict >, lowest index wins).
// Single block, 256 threads. Trivial cost.
// ---------------------------------------------------------------------------
__global__ void k2_fc_topk(const float* __restrict__ fc_w,
                           const float* __restrict__ fc_b) {
    __shared__ float mean_s[BB * CC];
    __shared__ float y_s[BB * CC];
    const int t = threadIdx.x;

    for (int i = t; i < BB * CC; i += 256) {
        float s = g_partial[i * NQ + 0] + g_partial[i * NQ + 1]
                + g_partial[i * NQ + 2] + g_partial[i * NQ + 3];
        mean_s[i] = s * (1.0f / (float)HW);
    }
    __syncthreads();

    for (int i = t; i < BB * CC; i += 256) {
        const int b = i >> 6;
        const int c = i & 63;
        float acc = fc_b[c];
#pragma unroll 8
        for (int j = 0; j < CC; j++)
            acc += mean_s[b * CC + j] * fc_w[c * CC + j];
        y_s[i] = (acc >= 0.0f) ? acc : 0.01f * acc;
    }
    __syncthreads();

    if (t < BB) {
        const int b = t;
        bool used[CC];
#pragma unroll
        for (int j = 0; j < CC; j++) used[j] = false;
        for (int kk = 0; kk < KK; kk++) {
            int best = 0;
            float bv = -3.402823466e38f;
            for (int j = 0; j < CC; j++) {
                float v = y_s[b * CC + j];
                if (!used[j] && v > bv) { bv = v; best = j; }
            }
            used[best] = true;
            g_idx[b * KK + kk] = best;
        }
    }
}

// ---------------------------------------------------------------------------
// Kernel 3: per-pixel Gaussian warp over selected channels.
// grid = (16, 256): blockIdx.y = b*32 + kk. Each thread does exactly 4
// float4 elements (loads front-batched for MLP), fast-math transcendentals,
// streaming stores. Reads sel (67 MB), writes swap + 4 aux maps (335 MB).
// ---------------------------------------------------------------------------
__global__ void k3_warp(const float* __restrict__ x,
                        const float* __restrict__ wox, const float* __restrict__ box_,
                        const float* __restrict__ woy, const float* __restrict__ boy,
                        const float* __restrict__ wsx, const float* __restrict__ bsx,
                        const float* __restrict__ wsy, const float* __restrict__ bsy,
                        float* __restrict__ out) {
    const int bk = blockIdx.y;      // 0..255
    const int b  = bk >> 5;
    const int kk = bk & 31;
    const int ch = g_idx[bk];

    const float wx = wox[kk], bx = box_[kk];
    const float wy = woy[kk], by = boy[kk];
    const float wsxk = wsx[kk], bsxk = bsx[kk];
    const float wsyk = wsy[kk], bsyk = bsy[kk];

    const float4* __restrict__ src =
        (const float4*)(x + ((size_t)b * CC + ch) * HW);
    float4* __restrict__ o_sw =
        (float4*)(out + OFF_OUT + ((size_t)b * 96 + 64 + kk) * HW);
    const size_t aux = (size_t)bk * HW;
    float4* __restrict__ o_px = (float4*)(out + OFF_PX + aux);
    float4* __restrict__ o_py = (float4*)(out + OFF_PY + aux);
    float4* __restrict__ o_sx = (float4*)(out + OFF_SX + aux);
    float4* __restrict__ o_sy = (float4*)(out + OFF_SY + aux);

    const int base = blockIdx.x * blockDim.x + threadIdx.x;  // 0..4095

    // Front-batch the 4 independent loads (MLP=4 per thread).
    float4 v[4];
#pragma unroll
    for (int m = 0; m < 4; m++)
        v[m] = __ldcs(&src[base + m * 4096]);

#pragma unroll
    for (int m = 0; m < 4; m++) {
        const int i4 = base + m * 4096;
        const float fi  = (float)(i4 >> 6);          // row (dim 2) coordinate
        const float fj0 = (float)((i4 & 63) << 2);   // col (dim 3) base coord

        float4 px, py, sx, sy, sw;

#define DO_LANE(comp, jo)                                                      \
        {                                                                      \
            float vv  = v[m].comp;                                             \
            float ex  = __fdividef(255.0f, 1.0f + __expf(-(wx * vv + bx)));    \
            float ey  = __fdividef(255.0f, 1.0f + __expf(-(wy * vv + by)));    \
            float sxx = fabsf(wsxk * vv + bsxk);                               \
            float syy = fabsf(wsyk * vv + bsyk);                               \
            float di  = fi - ex;                                               \
            float dj  = (fj0 + (jo)) - ey;                                     \
            float e   = __fdividef(di * di, 2.0f * sxx * sxx + 1e-6f)          \
                      + __fdividef(dj * dj, 2.0f * syy * syy + 1e-6f);         \
            float g   = __expf(-e);                                            \
            px.comp = ex; py.comp = ey;                                        \
            sx.comp = sxx; sy.comp = syy;                                      \
            sw.comp = vv * g;                                                  \
        }
        DO_LANE(x, 0.0f)
        DO_LANE(y, 1.0f)
        DO_LANE(z, 2.0f)
        DO_LANE(w, 3.0f)
#undef DO_LANE

        __stcs(&o_sw[i4], sw);
        __stcs(&o_px[i4], px);
        __stcs(&o_py[i4], py);
        __stcs(&o_sx[i4], sx);
        __stcs(&o_sy[i4], sy);
    }
}

// ---------------------------------------------------------------------------
extern "C" void kernel_launch(void* const* d_in, const int* in_sizes, int n_in,
                              void* d_out, int out_size) {
    const float* x    = (const float*)d_in[0];
    const float* fc_w = (const float*)d_in[1];
    const float* fc_b = (const float*)d_in[2];
    const float* wox  = (const float*)d_in[3];
    const float* box_ = (const float*)d_in[4];
    const float* woy  = (const float*)d_in[5];
    const float* boy  = (const float*)d_in[6];
    const float* wsx  = (const float*)d_in[7];
    const float* bsx  = (const float*)d_in[8];
    const float* wsy  = (const float*)d_in[9];
    const float* bsy  = (const float*)d_in[10];
    float* out = (float*)d_out;

    k1_mean_copy<<<BB * CC * NQ, 256>>>(x, out);
    k2_fc_topk<<<1, 256>>>(fc_w, fc_b);
    dim3 g3(16, BB * KK);
    k3_warp<<<g3, 256>>>(x, wox, box_, woy, boy, wsx, bsx, wsy, bsy, out);
}

// round 4
// speedup vs baseline: 1.1019x; 1.0732x over previous
#include <cuda_runtime.h>
#include <math.h>

// Problem constants
#define BB   8
#define CC   64
#define KK   32
#define WH   256
#define HW   65536          // 256*256 pixels per channel
#define NQ   4              // partial-sum quarters per channel

// Output packing (element offsets into d_out, fp32):
//   out  [8,96,256,256]  @ 0
//   exPx [8,32,256,256]  @ 50331648
//   exPy                 @ 67108864
//   sigmax               @ 83886080
//   sigmay               @ 100663296
#define OFF_OUT  0UL
#define OFF_PX   50331648UL
#define OFF_PY   67108864UL
#define OFF_SX   83886080UL
#define OFF_SY   100663296UL

// Scratch (no allocations allowed)
__device__ float g_partial[BB * CC * NQ];
__device__ int   g_idx[BB * KK];

// ---------------------------------------------------------------------------
// Kernel 1: stream x -> copy into out[:, :64] and accumulate per-channel sums.
// grid.x = 512 channels * 4 quarters = 2048 blocks, 256 threads.
// Plain loads/stores (streaming hints measured as a regression on this chip).
// ---------------------------------------------------------------------------
__global__ void __launch_bounds__(256)
k1_mean_copy(const float* __restrict__ x, float* __restrict__ out) {
    const int bc = blockIdx.x >> 2;   // 0..511 (b*64 + c)
    const int q  = blockIdx.x & 3;
    const int b  = bc >> 6;
    const int c  = bc & 63;

    const float4* __restrict__ src =
        (const float4*)(x + (size_t)bc * HW) + q * 4096;
    float4* __restrict__ dst =
        (float4*)(out + OFF_OUT + ((size_t)b * 96 + c) * HW) + q * 4096;

    float s = 0.0f;
#pragma unroll
    for (int it = 0; it < 16; it++) {
        float4 v = src[it * 256 + threadIdx.x];
        dst[it * 256 + threadIdx.x] = v;
        s += (v.x + v.y) + (v.z + v.w);
    }

    for (int off = 16; off > 0; off >>= 1)
        s += __shfl_down_sync(0xffffffffu, s, off);
    __shared__ float red[8];
    if ((threadIdx.x & 31) == 0) red[threadIdx.x >> 5] = s;
    __syncthreads();
    if (threadIdx.x == 0) {
        float t = 0.0f;
#pragma unroll
        for (int w = 0; w < 8; w++) t += red[w];
        g_partial[bc * NQ + q] = t;
    }
}

// ---------------------------------------------------------------------------
// Kernel 2: fold partials -> mean, FC (64x64) + LeakyReLU(0.01), then
// warp-parallel top-32 per batch. Channel values live in 2 registers per
// lane: NO local memory, no dynamic-index arrays. One warp per batch.
// jax.lax.top_k tie semantics: strict >, lowest index wins.
// ---------------------------------------------------------------------------
__global__ void __launch_bounds__(256)
k2_fc_topk(const float* __restrict__ fc_w, const float* __restrict__ fc_b) {
    __shared__ float mean_s[BB * CC];
    __shared__ float y_s[BB * CC];
    const int t = threadIdx.x;

    for (int i = t; i < BB * CC; i += 256) {
        float s = g_partial[i * NQ + 0] + g_partial[i * NQ + 1]
                + g_partial[i * NQ + 2] + g_partial[i * NQ + 3];
        mean_s[i] = s * (1.0f / (float)HW);
    }
    __syncthreads();

    for (int i = t; i < BB * CC; i += 256) {
        const int b = i >> 6;
        const int c = i & 63;
        float acc = fc_b[c];
#pragma unroll 8
        for (int j = 0; j < CC; j++)
            acc += mean_s[b * CC + j] * fc_w[c * CC + j];
        y_s[i] = (acc >= 0.0f) ? acc : 0.01f * acc;
    }
    __syncthreads();

    // warp w = batch w ; lane l owns channels l and l+32 (values in registers)
    const int b = t >> 5;
    const int l = t & 31;
    const float NEG = -3.402823466e38f;
    float v0 = y_s[b * CC + l];
    float v1 = y_s[b * CC + l + 32];

    for (int kk = 0; kk < KK; kk++) {
        // local best of the two candidates (tie -> lower index)
        float bv; int bi;
        if (v1 > v0) { bv = v1; bi = l + 32; } else { bv = v0; bi = l; }
        // warp argmax, tie -> lower index
#pragma unroll
        for (int off = 16; off > 0; off >>= 1) {
            float ov = __shfl_down_sync(0xffffffffu, bv, off);
            int   oi = __shfl_down_sync(0xffffffffu, bi, off);
            if (ov > bv || (ov == bv && oi < bi)) { bv = ov; bi = oi; }
        }
        bi = __shfl_sync(0xffffffffu, bi, 0);
        if (l == 0) g_idx[b * KK + kk] = bi;
        // retire the winner locally
        if (bi == l)      v0 = NEG;
        if (bi == l + 32) v1 = NEG;
    }
}

// ---------------------------------------------------------------------------
// Kernel 3: per-pixel Gaussian warp over selected channels.
// One float4 per thread. grid = (64, 256): blockIdx.y = b*32 + kk,
// blockIdx.x covers the 16384 float4 of one channel. Plain stores.
// Reads sel (67 MB), writes swap + 4 aux maps (335 MB).
// ---------------------------------------------------------------------------
__global__ void __launch_bounds__(256)
k3_warp(const float* __restrict__ x,
        const float* __restrict__ wox, const float* __restrict__ box_,
        const float* __restrict__ woy, const float* __restrict__ boy,
        const float* __restrict__ wsx, const float* __restrict__ bsx,
        const float* __restrict__ wsy, const float* __restrict__ bsy,
        float* __restrict__ out) {
    const int bk = blockIdx.y;      // 0..255
    const int b  = bk >> 5;
    const int kk = bk & 31;
    const int ch = g_idx[bk];

    const float wx = wox[kk], bx = box_[kk];
    const float wy = woy[kk], by = boy[kk];
    const float wsxk = wsx[kk], bsxk = bsx[kk];
    const float wsyk = wsy[kk], bsyk = bsy[kk];

    const float4* __restrict__ src =
        (const float4*)(x + ((size_t)b * CC + ch) * HW);
    float4* __restrict__ o_sw =
        (float4*)(out + OFF_OUT + ((size_t)b * 96 + 64 + kk) * HW);
    const size_t aux = (size_t)bk * HW;
    float4* __restrict__ o_px = (float4*)(out + OFF_PX + aux);
    float4* __restrict__ o_py = (float4*)(out + OFF_PY + aux);
    float4* __restrict__ o_sx = (float4*)(out + OFF_SX + aux);
    float4* __restrict__ o_sy = (float4*)(out + OFF_SY + aux);

    const int i4 = blockIdx.x * blockDim.x + threadIdx.x;  // 0..16383
    float4 v = src[i4];

    const float fi  = (float)(i4 >> 6);          // row (dim 2) coordinate
    const float fj0 = (float)((i4 & 63) << 2);   // col (dim 3) base coord

    float4 px, py, sx, sy, sw;

#define DO_LANE(comp, jo)                                                      \
    {                                                                          \
        float vv  = v.comp;                                                    \
        float ex  = __fdividef(255.0f, 1.0f + __expf(-(wx * vv + bx)));        \
        float ey  = __fdividef(255.0f, 1.0f + __expf(-(wy * vv + by)));        \
        float sxx = fabsf(wsxk * vv + bsxk);                                   \
        float syy = fabsf(wsyk * vv + bsyk);                                   \
        float di  = fi - ex;                                                   \
        float dj  = (fj0 + (jo)) - ey;                                         \
        float e   = __fdividef(di * di, 2.0f * sxx * sxx + 1e-6f)              \
                  + __fdividef(dj * dj, 2.0f * syy * syy + 1e-6f);             \
        float g   = __expf(-e);                                                \
        px.comp = ex; py.comp = ey;                                            \
        sx.comp = sxx; sy.comp = syy;                                          \
        sw.comp = vv * g;                                                      \
    }
    DO_LANE(x, 0.0f)
    DO_LANE(y, 1.0f)
    DO_LANE(z, 2.0f)
    DO_LANE(w, 3.0f)
#undef DO_LANE

    o_sw[i4] = sw;
    o_px[i4] = px;
    o_py[i4] = py;
    o_sx[i4] = sx;
    o_sy[i4] = sy;
}

// ---------------------------------------------------------------------------
extern "C" void kernel_launch(void* const* d_in, const int* in_sizes, int n_in,
                              void* d_out, int out_size) {
    const float* x    = (const float*)d_in[0];
    const float* fc_w = (const float*)d_in[1];
    const float* fc_b = (const float*)d_in[2];
    const float* wox  = (const float*)d_in[3];
    const float* box_ = (const float*)d_in[4];
    const float* woy  = (const float*)d_in[5];
    const float* boy  = (const float*)d_in[6];
    const float* wsx  = (const float*)d_in[7];
    const float* bsx  = (const float*)d_in[8];
    const float* wsy  = (const float*)d_in[9];
    const float* bsy  = (const float*)d_in[10];
    float* out = (float*)d_out;

    k1_mean_copy<<<BB * CC * NQ, 256>>>(x, out);
    k2_fc_topk<<<1, 256>>>(fc_w, fc_b);
    dim3 g3(64, BB * KK);
    k3_warp<<<g3, 256>>>(x, wox, box_, woy, boy, wsx, bsx, wsy, bsy, out);
}